// round 10
// baseline (speedup 1.0000x reference)
#include <cuda_runtime.h>
#include <cuda_bf16.h>
#include <math.h>
#include <stdint.h>

// Problem shape (fixed by the dataset)
#define BB 8
#define SS 2048
#define DD 1024

// Pre-split bf16 operand arrays (device globals — allocation-guard-safe)
__device__ __nv_bfloat16 g_xhi[(size_t)BB * SS * DD];
__device__ __nv_bfloat16 g_xlo[(size_t)BB * SS * DD];
__device__ __nv_bfloat16 g_xthi[(size_t)BB * SS * DD];
__device__ __nv_bfloat16 g_xtlo[(size_t)BB * SS * DD];
__device__ __nv_bfloat16 g_whi[(size_t)DD * DD];
__device__ __nv_bfloat16 g_wlo[(size_t)DD * DD];
__device__ __nv_bfloat16 g_phi[(size_t)BB * SS * DD];
__device__ __nv_bfloat16 g_plo[(size_t)BB * SS * DD];
__device__ __nv_bfloat16 g_ahi[(size_t)BB * SS * SS];
__device__ __nv_bfloat16 g_alo[(size_t)BB * SS * SS];

// ============================================================
// R10 GEMM: 256 threads, CTA tile 128(M) x 128(N), BK=32, 3-stage ring,
// ONE __syncthreads per chunk (96 MMAs/warp between barriers).
// 8 warps as 2m x 4n, warp tile 64x32.
// Pre-split bf16 hi/lo operands, 3 products (hh, hl, lh).
// Stage (32KB): Ahi 8K | Alo 8K | Bhi 8K | Blo 8K.  3 stages = 96KB.
// Ring-3 + one barrier: issue(ch+2) after iter-ch barrier overwrites the
// slot consumed in iter ch-1 (all warps past that barrier) -> safe.
// ============================================================

#define AH_OFF 0
#define AL_OFF 8192
#define BH_OFF 16384
#define BL_OFF 24576
#define STAGE_B 32768
#define GEMM_SMEM (3 * STAGE_B)   // 96 KB (>= epilogue's 67.6 KB)

__device__ __forceinline__ uint32_t smem_u32(const void* p) {
    uint32_t a;
    asm("{ .reg .u64 t; cvta.to.shared.u64 t, %1; cvt.u32.u64 %0, t; }" : "=r"(a) : "l"(p));
    return a;
}
// SW64 swizzle for 64-byte rows
__device__ __forceinline__ uint32_t sw64(uint32_t off) {
    return off ^ ((off >> 3) & 0x30);
}
__device__ __forceinline__ void ldsm_x4(uint32_t& r0, uint32_t& r1, uint32_t& r2, uint32_t& r3,
                                        uint32_t addr) {
    asm volatile("ldmatrix.sync.aligned.m8n8.x4.shared.b16 {%0,%1,%2,%3}, [%4];"
                 : "=r"(r0), "=r"(r1), "=r"(r2), "=r"(r3) : "r"(addr));
}
__device__ __forceinline__ void mma16816(float* d, const uint32_t* a, const uint32_t* b) {
    asm volatile(
        "mma.sync.aligned.m16n8k16.row.col.f32.bf16.bf16.f32 "
        "{%0,%1,%2,%3}, {%4,%5,%6,%7}, {%8,%9}, {%0,%1,%2,%3};"
        : "+f"(d[0]), "+f"(d[1]), "+f"(d[2]), "+f"(d[3])
        : "r"(a[0]), "r"(a[1]), "r"(a[2]), "r"(a[3]), "r"(b[0]), "r"(b[1]));
}

#define CP_ASYNC16(dst, src) \
    asm volatile("cp.async.cg.shared.global [%0], [%1], 16;" :: "r"(dst), "l"(src) : "memory")
#define CP_COMMIT()  asm volatile("cp.async.commit_group;" ::: "memory")
#define CP_WAIT1()   asm volatile("cp.async.wait_group 1;" ::: "memory")
#define CP_WAIT0()   asm volatile("cp.async.wait_group 0;" ::: "memory")

__device__ __forceinline__ void split2(const float4& v, uint2& hi, uint2& lo) {
    __nv_bfloat162 h0 = __floats2bfloat162_rn(v.x, v.y);
    __nv_bfloat162 h1 = __floats2bfloat162_rn(v.z, v.w);
    float r0 = v.x - __bfloat162float(__low2bfloat16(h0));
    float r1 = v.y - __bfloat162float(__high2bfloat16(h0));
    float r2 = v.z - __bfloat162float(__low2bfloat16(h1));
    float r3 = v.w - __bfloat162float(__high2bfloat16(h1));
    __nv_bfloat162 l0 = __floats2bfloat162_rn(r0, r1);
    __nv_bfloat162 l1 = __floats2bfloat162_rn(r2, r3);
    hi.x = *reinterpret_cast<uint32_t*>(&h0);
    hi.y = *reinterpret_cast<uint32_t*>(&h1);
    lo.x = *reinterpret_cast<uint32_t*>(&l0);
    lo.y = *reinterpret_cast<uint32_t*>(&l1);
}

__global__ __launch_bounds__(256, 2) void gemm_nt_mma(
    const __nv_bfloat16* __restrict__ Ahi, const __nv_bfloat16* __restrict__ Alo,
    const __nv_bfloat16* __restrict__ Bhi, const __nv_bfloat16* __restrict__ Blo,
    float* __restrict__ C, __nv_bfloat16* __restrict__ Chi, __nv_bfloat16* __restrict__ Clo,
    const float* __restrict__ bias,
    int M, int N, int K,
    long long strA, long long strB, long long strC)
{
    extern __shared__ __align__(1024) char smem[];
    const uint32_t sb = smem_u32(smem);
    const int tid = threadIdx.x, wid = tid >> 5, lane = tid & 31;
    const int row0 = blockIdx.y * 128, col0 = blockIdx.x * 128;

    Ahi += (size_t)blockIdx.z * strA;  Alo += (size_t)blockIdx.z * strA;
    Bhi += (size_t)blockIdx.z * strB;  Blo += (size_t)blockIdx.z * strB;

    // 2m x 4n warp grid, 64x32 warp tiles
    const int wm = wid & 1, wn = wid >> 1;
    const int m0w = wm * 64, n0w = wn * 32;

    // ---- cp.async loader (BK=32 -> 64B rows; A and B tiles both 128 rows) ----
    // 128 rows x 4 segs = 512 segs per tile; 256 thr -> 2 segs/thread.
    const int l_row = tid >> 1;
    const int l_s0  = (tid & 1) * 2;

    const __nv_bfloat16* gAhi = Ahi + (size_t)(row0 + l_row) * K + l_s0 * 8;
    const __nv_bfloat16* gAlo = Alo + (size_t)(row0 + l_row) * K + l_s0 * 8;
    const __nv_bfloat16* gBhi = Bhi + (size_t)(col0 + l_row) * K + l_s0 * 8;
    const __nv_bfloat16* gBlo = Blo + (size_t)(col0 + l_row) * K + l_s0 * 8;

    // ldmatrix lane addressing (64B rows)
    const uint32_t a_lrow = (uint32_t)(lane & 15);
    const uint32_t a_lc16 = (uint32_t)(lane >> 4) * 16;
    const uint32_t b_lrow = (uint32_t)((lane & 7) + ((lane >> 4) & 1) * 8);
    const uint32_t b_lk16 = (uint32_t)((lane >> 3) & 1) * 16;

    float acc[4][4][4];
#pragma unroll
    for (int i = 0; i < 4; i++)
#pragma unroll
        for (int j = 0; j < 4; j++)
#pragma unroll
            for (int q = 0; q < 4; q++) acc[i][j][q] = 0.f;

    const int NCH = K >> 5;   // BK=32

    auto issue = [&](int ch) {
        if (ch < NCH) {
            const uint32_t st = sb + (uint32_t)((ch % 3) * STAGE_B);
            const long long koff = (long long)(ch << 5);
            unsigned long long pah =
                (unsigned long long)__cvta_generic_to_global((const void*)(gAhi + koff));
            unsigned long long pal =
                (unsigned long long)__cvta_generic_to_global((const void*)(gAlo + koff));
            unsigned long long pbh =
                (unsigned long long)__cvta_generic_to_global((const void*)(gBhi + koff));
            unsigned long long pbl =
                (unsigned long long)__cvta_generic_to_global((const void*)(gBlo + koff));
#pragma unroll
            for (int s = 0; s < 2; s++) {
                uint32_t sw = sw64((uint32_t)(l_row * 64 + (l_s0 + s) * 16));
                CP_ASYNC16(st + AH_OFF + sw, pah + s * 16);
                CP_ASYNC16(st + AL_OFF + sw, pal + s * 16);
                CP_ASYNC16(st + BH_OFF + sw, pbh + s * 16);
                CP_ASYNC16(st + BL_OFF + sw, pbl + s * 16);
            }
        }
        CP_COMMIT();
    };

    // One k-step (k16): 12 LDSM.x4 -> 48 MMAs in 3 bursts of 16.
    auto mma_ks = [&](uint32_t base, int ks) {
        uint32_t aFh[4][4], bFh[4][2], bFl[4][2];
#pragma unroll
        for (int mf = 0; mf < 4; mf++) {
            uint32_t off = (uint32_t)((m0w + mf * 16 + a_lrow) * 64 + ks * 32 + a_lc16);
            ldsm_x4(aFh[mf][0], aFh[mf][1], aFh[mf][2], aFh[mf][3],
                    base + AH_OFF + sw64(off));
        }
#pragma unroll
        for (int nfp = 0; nfp < 2; nfp++) {
            uint32_t off = (uint32_t)((n0w + nfp * 16 + b_lrow) * 64 + ks * 32 + b_lk16);
            uint32_t r0, r1, r2, r3;
            ldsm_x4(r0, r1, r2, r3, base + BH_OFF + sw64(off));
            bFh[nfp * 2][0] = r0;      bFh[nfp * 2][1] = r1;
            bFh[nfp * 2 + 1][0] = r2;  bFh[nfp * 2 + 1][1] = r3;
        }
#pragma unroll
        for (int nfp = 0; nfp < 2; nfp++) {
            uint32_t off = (uint32_t)((n0w + nfp * 16 + b_lrow) * 64 + ks * 32 + b_lk16);
            uint32_t r0, r1, r2, r3;
            ldsm_x4(r0, r1, r2, r3, base + BL_OFF + sw64(off));
            bFl[nfp * 2][0] = r0;      bFl[nfp * 2][1] = r1;
            bFl[nfp * 2 + 1][0] = r2;  bFl[nfp * 2 + 1][1] = r3;
        }
        // burst 1: hh
#pragma unroll
        for (int mf = 0; mf < 4; mf++)
#pragma unroll
            for (int nf = 0; nf < 4; nf++) mma16816(acc[mf][nf], aFh[mf], bFh[nf]);
        // burst 2: hi(A) * lo(B)
#pragma unroll
        for (int mf = 0; mf < 4; mf++)
#pragma unroll
            for (int nf = 0; nf < 4; nf++) mma16816(acc[mf][nf], aFh[mf], bFl[nf]);
        // burst 3: lo(A) * hi(B)  (aFl loaded late to cap register liveness)
        uint32_t aFl[4][4];
#pragma unroll
        for (int mf = 0; mf < 4; mf++) {
            uint32_t off = (uint32_t)((m0w + mf * 16 + a_lrow) * 64 + ks * 32 + a_lc16);
            ldsm_x4(aFl[mf][0], aFl[mf][1], aFl[mf][2], aFl[mf][3],
                    base + AL_OFF + sw64(off));
        }
#pragma unroll
        for (int mf = 0; mf < 4; mf++)
#pragma unroll
            for (int nf = 0; nf < 4; nf++) mma16816(acc[mf][nf], aFl[mf], bFh[nf]);
    };

    // prologue: 2 stages in flight
    issue(0);
    issue(1);

    for (int ch = 0; ch < NCH; ch++) {
        const uint32_t cur = sb + (uint32_t)((ch % 3) * STAGE_B);
        CP_WAIT1();            // chunk ch resident (<=1 newer group pending)
        __syncthreads();       // ONE barrier per chunk
        issue(ch + 2);         // slot consumed in iter ch-1; all warps past barrier
        mma_ks(cur, 0);
        mma_ks(cur, 1);
    }
    CP_WAIT0();
    __syncthreads();

    // ---- epilogue: stage accums -> smem [128][132] -> coalesced writes ----
    float* eps = reinterpret_cast<float*>(smem);
    const int g = lane >> 2, c = lane & 3;
#pragma unroll
    for (int mf = 0; mf < 4; mf++)
#pragma unroll
        for (int nf = 0; nf < 4; nf++) {
            int r  = m0w + mf * 16 + g;
            int cc = n0w + nf * 8 + 2 * c;
            *reinterpret_cast<float2*>(&eps[r * 132 + cc]) =
                make_float2(acc[mf][nf][0], acc[mf][nf][1]);
            *reinterpret_cast<float2*>(&eps[(r + 8) * 132 + cc]) =
                make_float2(acc[mf][nf][2], acc[mf][nf][3]);
        }
    __syncthreads();

    if (Chi) {
        __nv_bfloat16* ph = Chi + (size_t)blockIdx.z * strC;
        __nv_bfloat16* pl = Clo + (size_t)blockIdx.z * strC;
#pragma unroll
        for (int it = 0; it < 16; it++) {
            int idx = tid + it * 256;
            int row = idx >> 5;
            int c4  = (idx & 31) << 2;
            float4 v = *reinterpret_cast<float4*>(&eps[row * 132 + c4]);
            float4 bz = *reinterpret_cast<const float4*>(&bias[col0 + c4]);
            v.x += bz.x; v.y += bz.y; v.z += bz.z; v.w += bz.w;
            uint2 hi, lo;
            split2(v, hi, lo);
            size_t o = (size_t)(row0 + row) * N + col0 + c4;
            *reinterpret_cast<uint2*>(&ph[o]) = hi;
            *reinterpret_cast<uint2*>(&pl[o]) = lo;
        }
    } else {
        float* Cb = C + (size_t)blockIdx.z * strC;
#pragma unroll
        for (int it = 0; it < 16; it++) {
            int idx = tid + it * 256;
            int row = idx >> 5;
            int c4  = (idx & 31) << 2;
            float4 v = *reinterpret_cast<float4*>(&eps[row * 132 + c4]);
            *reinterpret_cast<float4*>(&Cb[(size_t)(row0 + row) * N + col0 + c4]) = v;
        }
    }
}

// ============================================================
// prep_x: X -> X_hi/X_lo + XT_hi/XT_lo
// ============================================================
__global__ __launch_bounds__(256) void prep_x(
    const float* __restrict__ X,
    __nv_bfloat16* __restrict__ Xhi, __nv_bfloat16* __restrict__ Xlo,
    __nv_bfloat16* __restrict__ XThi, __nv_bfloat16* __restrict__ XTlo)
{
    __shared__ float t[32][33];
    const int b = blockIdx.z;
    const int s0 = blockIdx.x * 32, d0 = blockIdx.y * 32;
    const size_t bo = (size_t)b * SS * DD;
    const int tx = threadIdx.x, ty = threadIdx.y;
#pragma unroll
    for (int j = 0; j < 4; j++) {
        int s = s0 + ty + 8 * j;
        float v = X[bo + (size_t)s * DD + d0 + tx];
        t[ty + 8 * j][tx] = v;
        __nv_bfloat16 h = __float2bfloat16(v);
        Xhi[bo + (size_t)s * DD + d0 + tx] = h;
        Xlo[bo + (size_t)s * DD + d0 + tx] = __float2bfloat16(v - __bfloat162float(h));
    }
    __syncthreads();
#pragma unroll
    for (int j = 0; j < 4; j++) {
        int d = d0 + ty + 8 * j;
        float v = t[tx][ty + 8 * j];
        __nv_bfloat16 h = __float2bfloat16(v);
        XThi[bo + (size_t)d * SS + s0 + tx] = h;
        XTlo[bo + (size_t)d * SS + s0 + tx] = __float2bfloat16(v - __bfloat162float(h));
    }
}

__global__ __launch_bounds__(256) void split_w(
    const float* __restrict__ W,
    __nv_bfloat16* __restrict__ Whi, __nv_bfloat16* __restrict__ Wlo)
{
    int idx = blockIdx.x * 256 + threadIdx.x;
    float4 v = reinterpret_cast<const float4*>(W)[idx];
    uint2 hi, lo;
    split2(v, hi, lo);
    reinterpret_cast<uint2*>(Whi)[idx] = hi;
    reinterpret_cast<uint2*>(Wlo)[idx] = lo;
}

// ============================================================
// In-place row softmax + split bf16 out
// ============================================================
__device__ __forceinline__ float warp_max(float v) {
#pragma unroll
    for (int o = 16; o > 0; o >>= 1) v = fmaxf(v, __shfl_xor_sync(0xFFFFFFFFu, v, o));
    return v;
}
__device__ __forceinline__ float warp_sum(float v) {
#pragma unroll
    for (int o = 16; o > 0; o >>= 1) v += __shfl_xor_sync(0xFFFFFFFFu, v, o);
    return v;
}

__global__ __launch_bounds__(256) void softmax_rows(
    float* __restrict__ attn,
    __nv_bfloat16* __restrict__ Ahi, __nv_bfloat16* __restrict__ Alo)
{
    __shared__ float red[8];
    const size_t ro = (size_t)blockIdx.x * SS;
    float* row = attn + ro;
    const int tid = threadIdx.x, lane = tid & 31, wid = tid >> 5;

    float4 v[2];
    v[0] = *reinterpret_cast<const float4*>(&row[tid * 4]);
    v[1] = *reinterpret_cast<const float4*>(&row[(tid + 256) * 4]);

    float mx = -INFINITY;
#pragma unroll
    for (int i = 0; i < 2; i++)
        mx = fmaxf(mx, fmaxf(fmaxf(v[i].x, v[i].y), fmaxf(v[i].z, v[i].w)));
    mx = warp_max(mx);
    if (lane == 0) red[wid] = mx;
    __syncthreads();
    if (wid == 0) {
        float t = (lane < 8) ? red[lane] : -INFINITY;
        t = warp_max(t);
        if (lane == 0) red[0] = t;
    }
    __syncthreads();
    mx = red[0];
    __syncthreads();

    float s = 0.f;
#pragma unroll
    for (int i = 0; i < 2; i++) {
        v[i].x = expf(v[i].x - mx); s += v[i].x;
        v[i].y = expf(v[i].y - mx); s += v[i].y;
        v[i].z = expf(v[i].z - mx); s += v[i].z;
        v[i].w = expf(v[i].w - mx); s += v[i].w;
    }
    s = warp_sum(s);
    if (lane == 0) red[wid] = s;
    __syncthreads();
    if (wid == 0) {
        float t = (lane < 8) ? red[lane] : 0.0f;
        t = warp_sum(t);
        if (lane == 0) red[0] = t;
    }
    __syncthreads();
    float inv = 1.0f / red[0];

#pragma unroll
    for (int i = 0; i < 2; i++) { v[i].x *= inv; v[i].y *= inv; v[i].z *= inv; v[i].w *= inv; }
    *reinterpret_cast<float4*>(&row[tid * 4])         = v[0];
    *reinterpret_cast<float4*>(&row[(tid + 256) * 4]) = v[1];

    uint2 hi, lo;
    split2(v[0], hi, lo);
    *reinterpret_cast<uint2*>(&Ahi[ro + tid * 4]) = hi;
    *reinterpret_cast<uint2*>(&Alo[ro + tid * 4]) = lo;
    split2(v[1], hi, lo);
    *reinterpret_cast<uint2*>(&Ahi[ro + (tid + 256) * 4]) = hi;
    *reinterpret_cast<uint2*>(&Alo[ro + (tid + 256) * 4]) = lo;
}

// ============================================================
// kernel_launch
// ============================================================
extern "C" void kernel_launch(void* const* d_in, const int* in_sizes, int n_in,
                              void* d_out, int out_size)
{
    const float* X    = (const float*)d_in[0];
    const float* W    = (const float*)d_in[1];
    const float* bias = (const float*)d_in[2];

    float* ctx  = (float*)d_out;                           // [8,2048,1024]
    float* attn = (float*)d_out + (size_t)BB * SS * DD;    // [8,2048,2048]

    __nv_bfloat16 *xhi, *xlo, *xthi, *xtlo, *whi, *wlo, *phi, *plo, *ahi, *alo;
    cudaGetSymbolAddress((void**)&xhi,  g_xhi);
    cudaGetSymbolAddress((void**)&xlo,  g_xlo);
    cudaGetSymbolAddress((void**)&xthi, g_xthi);
    cudaGetSymbolAddress((void**)&xtlo, g_xtlo);
    cudaGetSymbolAddress((void**)&whi,  g_whi);
    cudaGetSymbolAddress((void**)&wlo,  g_wlo);
    cudaGetSymbolAddress((void**)&phi,  g_phi);
    cudaGetSymbolAddress((void**)&plo,  g_plo);
    cudaGetSymbolAddress((void**)&ahi,  g_ahi);
    cudaGetSymbolAddress((void**)&alo,  g_alo);

    cudaFuncSetAttribute(gemm_nt_mma, cudaFuncAttributeMaxDynamicSharedMemorySize, GEMM_SMEM);

    const long long sXD = (long long)SS * DD;
    const long long sAA = (long long)SS * SS;

    {
        dim3 grid(SS / 32, DD / 32, BB);
        prep_x<<<grid, dim3(32, 8)>>>(X, xhi, xlo, xthi, xtlo);
    }
    split_w<<<(DD * DD / 4) / 256, 256>>>(W, whi, wlo);

    // GEMM1: proj = X * W^T + b  -> split bf16 pair
    {
        dim3 grid(DD / 128, (BB * SS) / 128, 1);
        gemm_nt_mma<<<grid, 256, GEMM_SMEM>>>(xhi, xlo, whi, wlo,
                                              nullptr, phi, plo, bias,
                                              BB * SS, DD, DD, 0, 0, 0);
    }
    // GEMM2: attn[b] = X[b] * proj[b]^T  (fp32 out)
    {
        dim3 grid(SS / 128, SS / 128, BB);
        gemm_nt_mma<<<grid, 256, GEMM_SMEM>>>(xhi, xlo, phi, plo,
                                              attn, nullptr, nullptr, nullptr,
                                              SS, SS, DD, sXD, sXD, sAA);
    }
    softmax_rows<<<BB * SS, 256>>>(attn, ahi, alo);
    // GEMM3: ctx[b] = attn[b] * XT[b]^T  (fp32 out)
    {
        dim3 grid(DD / 128, SS / 128, BB);
        gemm_nt_mma<<<grid, 256, GEMM_SMEM>>>(ahi, alo, xthi, xtlo,
                                              ctx, nullptr, nullptr, nullptr,
                                              SS, DD, SS, sAA, sXD, sXD);
    }
}

// round 11
// speedup vs baseline: 1.0921x; 1.0921x over previous
#include <cuda_runtime.h>
#include <cuda_bf16.h>
#include <math.h>
#include <stdint.h>

// Problem shape (fixed by the dataset)
#define BB 8
#define SS 2048
#define DD 1024

// Pre-split bf16 operand arrays (device globals — allocation-guard-safe)
__device__ __nv_bfloat16 g_xhi[(size_t)BB * SS * DD];
__device__ __nv_bfloat16 g_xlo[(size_t)BB * SS * DD];
__device__ __nv_bfloat16 g_xthi[(size_t)BB * SS * DD];
__device__ __nv_bfloat16 g_xtlo[(size_t)BB * SS * DD];
__device__ __nv_bfloat16 g_whi[(size_t)DD * DD];
__device__ __nv_bfloat16 g_wlo[(size_t)DD * DD];
__device__ __nv_bfloat16 g_phi[(size_t)BB * SS * DD];
__device__ __nv_bfloat16 g_plo[(size_t)BB * SS * DD];
__device__ __nv_bfloat16 g_ahi[(size_t)BB * SS * SS];
__device__ __nv_bfloat16 g_alo[(size_t)BB * SS * SS];

// ============================================================
// R11 GEMM: R9 datapath (BK=16 stages, 64x32 warp tiles, 1-seg cp.async)
// with a 6-stage ring consuming TWO chunks per barrier:
//   CP_WAIT2 -> sync -> issue(2i+4), issue(2i+5) -> mma(2i), mma(2i+1)
// 96 MMAs/warp between barriers (R10 cadence) at R9 register pressure
// and R9 prefetch depth.
// Stage (16KB): Ahi 4K | Alo 4K | Bhi 4K | Blo 4K.  6 stages = 96KB.
// ============================================================

#define AH_OFF 0
#define AL_OFF 4096
#define BH_OFF 8192
#define BL_OFF 12288
#define STAGE_B 16384
#define GEMM_SMEM (6 * STAGE_B)   // 96 KB (>= epilogue's 67.6 KB)

__device__ __forceinline__ uint32_t smem_u32(const void* p) {
    uint32_t a;
    asm("{ .reg .u64 t; cvta.to.shared.u64 t, %1; cvt.u32.u64 %0, t; }" : "=r"(a) : "l"(p));
    return a;
}
// Swizzle for 32-byte rows: XOR row bit 2 into 16B-seg select bit.
__device__ __forceinline__ uint32_t sw32(uint32_t off) {
    return off ^ ((off >> 3) & 0x10);
}
__device__ __forceinline__ void ldsm_x4(uint32_t& r0, uint32_t& r1, uint32_t& r2, uint32_t& r3,
                                        uint32_t addr) {
    asm volatile("ldmatrix.sync.aligned.m8n8.x4.shared.b16 {%0,%1,%2,%3}, [%4];"
                 : "=r"(r0), "=r"(r1), "=r"(r2), "=r"(r3) : "r"(addr));
}
__device__ __forceinline__ void mma16816(float* d, const uint32_t* a, const uint32_t* b) {
    asm volatile(
        "mma.sync.aligned.m16n8k16.row.col.f32.bf16.bf16.f32 "
        "{%0,%1,%2,%3}, {%4,%5,%6,%7}, {%8,%9}, {%0,%1,%2,%3};"
        : "+f"(d[0]), "+f"(d[1]), "+f"(d[2]), "+f"(d[3])
        : "r"(a[0]), "r"(a[1]), "r"(a[2]), "r"(a[3]), "r"(b[0]), "r"(b[1]));
}

#define CP_ASYNC16(dst, src) \
    asm volatile("cp.async.cg.shared.global [%0], [%1], 16;" :: "r"(dst), "l"(src) : "memory")
#define CP_COMMIT()  asm volatile("cp.async.commit_group;" ::: "memory")
#define CP_WAIT2()   asm volatile("cp.async.wait_group 2;" ::: "memory")
#define CP_WAIT0()   asm volatile("cp.async.wait_group 0;" ::: "memory")

__device__ __forceinline__ void split2(const float4& v, uint2& hi, uint2& lo) {
    __nv_bfloat162 h0 = __floats2bfloat162_rn(v.x, v.y);
    __nv_bfloat162 h1 = __floats2bfloat162_rn(v.z, v.w);
    float r0 = v.x - __bfloat162float(__low2bfloat16(h0));
    float r1 = v.y - __bfloat162float(__high2bfloat16(h0));
    float r2 = v.z - __bfloat162float(__low2bfloat16(h1));
    float r3 = v.w - __bfloat162float(__high2bfloat16(h1));
    __nv_bfloat162 l0 = __floats2bfloat162_rn(r0, r1);
    __nv_bfloat162 l1 = __floats2bfloat162_rn(r2, r3);
    hi.x = *reinterpret_cast<uint32_t*>(&h0);
    hi.y = *reinterpret_cast<uint32_t*>(&h1);
    lo.x = *reinterpret_cast<uint32_t*>(&l0);
    lo.y = *reinterpret_cast<uint32_t*>(&l1);
}

__global__ __launch_bounds__(256, 2) void gemm_nt_mma(
    const __nv_bfloat16* __restrict__ Ahi, const __nv_bfloat16* __restrict__ Alo,
    const __nv_bfloat16* __restrict__ Bhi, const __nv_bfloat16* __restrict__ Blo,
    float* __restrict__ C, __nv_bfloat16* __restrict__ Chi, __nv_bfloat16* __restrict__ Clo,
    const float* __restrict__ bias,
    int M, int N, int K,
    long long strA, long long strB, long long strC)
{
    extern __shared__ __align__(1024) char smem[];
    const uint32_t sb = smem_u32(smem);
    const int tid = threadIdx.x, wid = tid >> 5, lane = tid & 31;
    const int row0 = blockIdx.y * 128, col0 = blockIdx.x * 128;

    Ahi += (size_t)blockIdx.z * strA;  Alo += (size_t)blockIdx.z * strA;
    Bhi += (size_t)blockIdx.z * strB;  Blo += (size_t)blockIdx.z * strB;

    // 2m x 4n warp grid, 64x32 warp tiles
    const int wm = wid & 1, wn = wid >> 1;
    const int m0w = wm * 64, n0w = wn * 32;

    // ---- cp.async loader indexing (BK=16 -> 32B rows, 1 seg/thread/tile) ----
    const int l_row = tid >> 1;       // 0..127
    const int l_s   = tid & 1;        // 16B seg within row

    const __nv_bfloat16* gAhi = Ahi + (size_t)(row0 + l_row) * K + l_s * 8;
    const __nv_bfloat16* gAlo = Alo + (size_t)(row0 + l_row) * K + l_s * 8;
    const __nv_bfloat16* gBhi = Bhi + (size_t)(col0 + l_row) * K + l_s * 8;
    const __nv_bfloat16* gBlo = Blo + (size_t)(col0 + l_row) * K + l_s * 8;

    // ldmatrix lane addressing (32B rows)
    const uint32_t a_lrow = (uint32_t)(lane & 15);
    const uint32_t a_lc16 = (uint32_t)(lane >> 4) * 16;
    const uint32_t b_lrow = (uint32_t)((lane & 7) + ((lane >> 4) & 1) * 8);
    const uint32_t b_lk16 = (uint32_t)((lane >> 3) & 1) * 16;

    float acc[4][4][4];
#pragma unroll
    for (int i = 0; i < 4; i++)
#pragma unroll
        for (int j = 0; j < 4; j++)
#pragma unroll
            for (int q = 0; q < 4; q++) acc[i][j][q] = 0.f;

    const int NCH = K >> 4;   // BK=16; always even here

    auto issue = [&](int ch) {
        if (ch < NCH) {
            const uint32_t st = sb + (uint32_t)((ch % 6) * STAGE_B);
            const long long koff = (long long)(ch << 4);
            unsigned long long pah =
                (unsigned long long)__cvta_generic_to_global((const void*)(gAhi + koff));
            unsigned long long pal =
                (unsigned long long)__cvta_generic_to_global((const void*)(gAlo + koff));
            unsigned long long pbh =
                (unsigned long long)__cvta_generic_to_global((const void*)(gBhi + koff));
            unsigned long long pbl =
                (unsigned long long)__cvta_generic_to_global((const void*)(gBlo + koff));
            uint32_t sw = sw32((uint32_t)(l_row * 32 + l_s * 16));
            CP_ASYNC16(st + AH_OFF + sw, pah);
            CP_ASYNC16(st + AL_OFF + sw, pal);
            CP_ASYNC16(st + BH_OFF + sw, pbh);
            CP_ASYNC16(st + BL_OFF + sw, pbl);
        }
        CP_COMMIT();
    };

    // One chunk (k16): 12 LDSM.x4 -> 48 MMAs in 3 bursts of 16.
    auto mma_ks = [&](uint32_t base) {
        uint32_t aFh[4][4], bFh[4][2], bFl[4][2];
#pragma unroll
        for (int mf = 0; mf < 4; mf++) {
            uint32_t off = (uint32_t)((m0w + mf * 16 + a_lrow) * 32 + a_lc16);
            ldsm_x4(aFh[mf][0], aFh[mf][1], aFh[mf][2], aFh[mf][3],
                    base + AH_OFF + sw32(off));
        }
#pragma unroll
        for (int nfp = 0; nfp < 2; nfp++) {
            uint32_t off = (uint32_t)((n0w + nfp * 16 + b_lrow) * 32 + b_lk16);
            uint32_t r0, r1, r2, r3;
            ldsm_x4(r0, r1, r2, r3, base + BH_OFF + sw32(off));
            bFh[nfp * 2][0] = r0;      bFh[nfp * 2][1] = r1;
            bFh[nfp * 2 + 1][0] = r2;  bFh[nfp * 2 + 1][1] = r3;
        }
#pragma unroll
        for (int nfp = 0; nfp < 2; nfp++) {
            uint32_t off = (uint32_t)((n0w + nfp * 16 + b_lrow) * 32 + b_lk16);
            uint32_t r0, r1, r2, r3;
            ldsm_x4(r0, r1, r2, r3, base + BL_OFF + sw32(off));
            bFl[nfp * 2][0] = r0;      bFl[nfp * 2][1] = r1;
            bFl[nfp * 2 + 1][0] = r2;  bFl[nfp * 2 + 1][1] = r3;
        }
        // burst 1: hh
#pragma unroll
        for (int mf = 0; mf < 4; mf++)
#pragma unroll
            for (int nf = 0; nf < 4; nf++) mma16816(acc[mf][nf], aFh[mf], bFh[nf]);
        // burst 2: hi(A) * lo(B)
#pragma unroll
        for (int mf = 0; mf < 4; mf++)
#pragma unroll
            for (int nf = 0; nf < 4; nf++) mma16816(acc[mf][nf], aFh[mf], bFl[nf]);
        // burst 3: lo(A) * hi(B)  (aFl loaded late to cap register liveness)
        uint32_t aFl[4][4];
#pragma unroll
        for (int mf = 0; mf < 4; mf++) {
            uint32_t off = (uint32_t)((m0w + mf * 16 + a_lrow) * 32 + a_lc16);
            ldsm_x4(aFl[mf][0], aFl[mf][1], aFl[mf][2], aFl[mf][3],
                    base + AL_OFF + sw32(off));
        }
#pragma unroll
        for (int mf = 0; mf < 4; mf++)
#pragma unroll
            for (int nf = 0; nf < 4; nf++) mma16816(acc[mf][nf], aFl[mf], bFh[nf]);
    };

    // prologue: 4 chunks in flight
    issue(0);
    issue(1);
    issue(2);
    issue(3);

    const int NPAIR = NCH >> 1;
    for (int i = 0; i < NPAIR; i++) {
        const int ch = 2 * i;
        const uint32_t s0 = sb + (uint32_t)((ch % 6) * STAGE_B);
        const uint32_t s1 = sb + (uint32_t)(((ch + 1) % 6) * STAGE_B);
        CP_WAIT2();            // chunks ch, ch+1 resident (<=2 newer groups pending)
        __syncthreads();       // ONE barrier per pair (96 MMAs/warp)
        issue(ch + 4);         // stage (ch+4)%6: consumed as chunk ch-2 in iter i-1
        issue(ch + 5);         // stage (ch+5)%6: consumed as chunk ch-1 in iter i-1
        mma_ks(s0);
        mma_ks(s1);
    }
    CP_WAIT0();
    __syncthreads();

    // ---- epilogue: stage accums -> smem [128][132] -> coalesced writes ----
    float* eps = reinterpret_cast<float*>(smem);
    const int g = lane >> 2, c = lane & 3;
#pragma unroll
    for (int mf = 0; mf < 4; mf++)
#pragma unroll
        for (int nf = 0; nf < 4; nf++) {
            int r  = m0w + mf * 16 + g;
            int cc = n0w + nf * 8 + 2 * c;
            *reinterpret_cast<float2*>(&eps[r * 132 + cc]) =
                make_float2(acc[mf][nf][0], acc[mf][nf][1]);
            *reinterpret_cast<float2*>(&eps[(r + 8) * 132 + cc]) =
                make_float2(acc[mf][nf][2], acc[mf][nf][3]);
        }
    __syncthreads();

    if (Chi) {
        __nv_bfloat16* ph = Chi + (size_t)blockIdx.z * strC;
        __nv_bfloat16* pl = Clo + (size_t)blockIdx.z * strC;
#pragma unroll
        for (int it = 0; it < 16; it++) {
            int idx = tid + it * 256;
            int row = idx >> 5;
            int c4  = (idx & 31) << 2;
            float4 v = *reinterpret_cast<float4*>(&eps[row * 132 + c4]);
            float4 bz = *reinterpret_cast<const float4*>(&bias[col0 + c4]);
            v.x += bz.x; v.y += bz.y; v.z += bz.z; v.w += bz.w;
            uint2 hi, lo;
            split2(v, hi, lo);
            size_t o = (size_t)(row0 + row) * N + col0 + c4;
            *reinterpret_cast<uint2*>(&ph[o]) = hi;
            *reinterpret_cast<uint2*>(&pl[o]) = lo;
        }
    } else {
        float* Cb = C + (size_t)blockIdx.z * strC;
#pragma unroll
        for (int it = 0; it < 16; it++) {
            int idx = tid + it * 256;
            int row = idx >> 5;
            int c4  = (idx & 31) << 2;
            float4 v = *reinterpret_cast<float4*>(&eps[row * 132 + c4]);
            *reinterpret_cast<float4*>(&Cb[(size_t)(row0 + row) * N + col0 + c4]) = v;
        }
    }
}

// ============================================================
// prep_x: X -> X_hi/X_lo + XT_hi/XT_lo
// ============================================================
__global__ __launch_bounds__(256) void prep_x(
    const float* __restrict__ X,
    __nv_bfloat16* __restrict__ Xhi, __nv_bfloat16* __restrict__ Xlo,
    __nv_bfloat16* __restrict__ XThi, __nv_bfloat16* __restrict__ XTlo)
{
    __shared__ float t[32][33];
    const int b = blockIdx.z;
    const int s0 = blockIdx.x * 32, d0 = blockIdx.y * 32;
    const size_t bo = (size_t)b * SS * DD;
    const int tx = threadIdx.x, ty = threadIdx.y;
#pragma unroll
    for (int j = 0; j < 4; j++) {
        int s = s0 + ty + 8 * j;
        float v = X[bo + (size_t)s * DD + d0 + tx];
        t[ty + 8 * j][tx] = v;
        __nv_bfloat16 h = __float2bfloat16(v);
        Xhi[bo + (size_t)s * DD + d0 + tx] = h;
        Xlo[bo + (size_t)s * DD + d0 + tx] = __float2bfloat16(v - __bfloat162float(h));
    }
    __syncthreads();
#pragma unroll
    for (int j = 0; j < 4; j++) {
        int d = d0 + ty + 8 * j;
        float v = t[tx][ty + 8 * j];
        __nv_bfloat16 h = __float2bfloat16(v);
        XThi[bo + (size_t)d * SS + s0 + tx] = h;
        XTlo[bo + (size_t)d * SS + s0 + tx] = __float2bfloat16(v - __bfloat162float(h));
    }
}

__global__ __launch_bounds__(256) void split_w(
    const float* __restrict__ W,
    __nv_bfloat16* __restrict__ Whi, __nv_bfloat16* __restrict__ Wlo)
{
    int idx = blockIdx.x * 256 + threadIdx.x;
    float4 v = reinterpret_cast<const float4*>(W)[idx];
    uint2 hi, lo;
    split2(v, hi, lo);
    reinterpret_cast<uint2*>(Whi)[idx] = hi;
    reinterpret_cast<uint2*>(Wlo)[idx] = lo;
}

// ============================================================
// In-place row softmax + split bf16 out
// ============================================================
__device__ __forceinline__ float warp_max(float v) {
#pragma unroll
    for (int o = 16; o > 0; o >>= 1) v = fmaxf(v, __shfl_xor_sync(0xFFFFFFFFu, v, o));
    return v;
}
__device__ __forceinline__ float warp_sum(float v) {
#pragma unroll
    for (int o = 16; o > 0; o >>= 1) v += __shfl_xor_sync(0xFFFFFFFFu, v, o);
    return v;
}

__global__ __launch_bounds__(256) void softmax_rows(
    float* __restrict__ attn,
    __nv_bfloat16* __restrict__ Ahi, __nv_bfloat16* __restrict__ Alo)
{
    __shared__ float red[8];
    const size_t ro = (size_t)blockIdx.x * SS;
    float* row = attn + ro;
    const int tid = threadIdx.x, lane = tid & 31, wid = tid >> 5;

    float4 v[2];
    v[0] = *reinterpret_cast<const float4*>(&row[tid * 4]);
    v[1] = *reinterpret_cast<const float4*>(&row[(tid + 256) * 4]);

    float mx = -INFINITY;
#pragma unroll
    for (int i = 0; i < 2; i++)
        mx = fmaxf(mx, fmaxf(fmaxf(v[i].x, v[i].y), fmaxf(v[i].z, v[i].w)));
    mx = warp_max(mx);
    if (lane == 0) red[wid] = mx;
    __syncthreads();
    if (wid == 0) {
        float t = (lane < 8) ? red[lane] : -INFINITY;
        t = warp_max(t);
        if (lane == 0) red[0] = t;
    }
    __syncthreads();
    mx = red[0];
    __syncthreads();

    float s = 0.f;
#pragma unroll
    for (int i = 0; i < 2; i++) {
        v[i].x = expf(v[i].x - mx); s += v[i].x;
        v[i].y = expf(v[i].y - mx); s += v[i].y;
        v[i].z = expf(v[i].z - mx); s += v[i].z;
        v[i].w = expf(v[i].w - mx); s += v[i].w;
    }
    s = warp_sum(s);
    if (lane == 0) red[wid] = s;
    __syncthreads();
    if (wid == 0) {
        float t = (lane < 8) ? red[lane] : 0.0f;
        t = warp_sum(t);
        if (lane == 0) red[0] = t;
    }
    __syncthreads();
    float inv = 1.0f / red[0];

#pragma unroll
    for (int i = 0; i < 2; i++) { v[i].x *= inv; v[i].y *= inv; v[i].z *= inv; v[i].w *= inv; }
    *reinterpret_cast<float4*>(&row[tid * 4])         = v[0];
    *reinterpret_cast<float4*>(&row[(tid + 256) * 4]) = v[1];

    uint2 hi, lo;
    split2(v[0], hi, lo);
    *reinterpret_cast<uint2*>(&Ahi[ro + tid * 4]) = hi;
    *reinterpret_cast<uint2*>(&Alo[ro + tid * 4]) = lo;
    split2(v[1], hi, lo);
    *reinterpret_cast<uint2*>(&Ahi[ro + (tid + 256) * 4]) = hi;
    *reinterpret_cast<uint2*>(&Alo[ro + (tid + 256) * 4]) = lo;
}

// ============================================================
// kernel_launch
// ============================================================
extern "C" void kernel_launch(void* const* d_in, const int* in_sizes, int n_in,
                              void* d_out, int out_size)
{
    const float* X    = (const float*)d_in[0];
    const float* W    = (const float*)d_in[1];
    const float* bias = (const float*)d_in[2];

    float* ctx  = (float*)d_out;                           // [8,2048,1024]
    float* attn = (float*)d_out + (size_t)BB * SS * DD;    // [8,2048,2048]

    __nv_bfloat16 *xhi, *xlo, *xthi, *xtlo, *whi, *wlo, *phi, *plo, *ahi, *alo;
    cudaGetSymbolAddress((void**)&xhi,  g_xhi);
    cudaGetSymbolAddress((void**)&xlo,  g_xlo);
    cudaGetSymbolAddress((void**)&xthi, g_xthi);
    cudaGetSymbolAddress((void**)&xtlo, g_xtlo);
    cudaGetSymbolAddress((void**)&whi,  g_whi);
    cudaGetSymbolAddress((void**)&wlo,  g_wlo);
    cudaGetSymbolAddress((void**)&phi,  g_phi);
    cudaGetSymbolAddress((void**)&plo,  g_plo);
    cudaGetSymbolAddress((void**)&ahi,  g_ahi);
    cudaGetSymbolAddress((void**)&alo,  g_alo);

    cudaFuncSetAttribute(gemm_nt_mma, cudaFuncAttributeMaxDynamicSharedMemorySize, GEMM_SMEM);

    const long long sXD = (long long)SS * DD;
    const long long sAA = (long long)SS * SS;

    {
        dim3 grid(SS / 32, DD / 32, BB);
        prep_x<<<grid, dim3(32, 8)>>>(X, xhi, xlo, xthi, xtlo);
    }
    split_w<<<(DD * DD / 4) / 256, 256>>>(W, whi, wlo);

    // GEMM1: proj = X * W^T + b  -> split bf16 pair
    {
        dim3 grid(DD / 128, (BB * SS) / 128, 1);
        gemm_nt_mma<<<grid, 256, GEMM_SMEM>>>(xhi, xlo, whi, wlo,
                                              nullptr, phi, plo, bias,
                                              BB * SS, DD, DD, 0, 0, 0);
    }
    // GEMM2: attn[b] = X[b] * proj[b]^T  (fp32 out)
    {
        dim3 grid(SS / 128, SS / 128, BB);
        gemm_nt_mma<<<grid, 256, GEMM_SMEM>>>(xhi, xlo, phi, plo,
                                              attn, nullptr, nullptr, nullptr,
                                              SS, SS, DD, sXD, sXD, sAA);
    }
    softmax_rows<<<BB * SS, 256>>>(attn, ahi, alo);
    // GEMM3: ctx[b] = attn[b] * XT[b]^T  (fp32 out)
    {
        dim3 grid(DD / 128, SS / 128, BB);
        gemm_nt_mma<<<grid, 256, GEMM_SMEM>>>(ahi, alo, xthi, xtlo,
                                              ctx, nullptr, nullptr, nullptr,
                                              SS, DD, SS, sAA, sXD, sXD);
    }
}

// round 12
// speedup vs baseline: 1.1382x; 1.0423x over previous
#include <cuda_runtime.h>
#include <cuda_bf16.h>
#include <math.h>
#include <stdint.h>

// Problem shape (fixed by the dataset)
#define BB 8
#define SS 2048
#define DD 1024

// Pre-split bf16 operand arrays (device globals — allocation-guard-safe)
__device__ __nv_bfloat16 g_xhi[(size_t)BB * SS * DD];
__device__ __nv_bfloat16 g_xlo[(size_t)BB * SS * DD];
__device__ __nv_bfloat16 g_xthi[(size_t)BB * SS * DD];
__device__ __nv_bfloat16 g_xtlo[(size_t)BB * SS * DD];
__device__ __nv_bfloat16 g_whi[(size_t)DD * DD];
__device__ __nv_bfloat16 g_wlo[(size_t)DD * DD];
__device__ __nv_bfloat16 g_phi[(size_t)BB * SS * DD];
__device__ __nv_bfloat16 g_plo[(size_t)BB * SS * DD];
__device__ __nv_bfloat16 g_ahi[(size_t)BB * SS * SS];
__device__ __nv_bfloat16 g_alo[(size_t)BB * SS * SS];

// ============================================================
// R12 GEMM: 256 threads, CTA tile 128(M) x 64(N), BK=16, 4-stage ring,
// ONE __syncthreads per chunk, *** 3 CTAs/SM (6 warps/SMSP) ***.
// 8 warps as 4m x 2n, warp tile 32x32 (acc = 32 regs -> ~84 live regs).
// Pre-split bf16 hi/lo operands, 3 products (hh, hl, lh).
// Stage (12KB): Ahi 4K | Alo 4K | Bhi 2K | Blo 2K.  4 stages = 48KB.
// 3 CTAs x 48KB = 144KB smem/SM; 3 x 256 x 85 regs = 65280 <= 65536.
// ============================================================

#define AH_OFF 0
#define AL_OFF 4096
#define BH_OFF 8192
#define BL_OFF 10240
#define STAGE_B 12288
#define GEMM_SMEM (4 * STAGE_B)   // 48 KB (>= epilogue's 34.8 KB)

__device__ __forceinline__ uint32_t smem_u32(const void* p) {
    uint32_t a;
    asm("{ .reg .u64 t; cvta.to.shared.u64 t, %1; cvt.u32.u64 %0, t; }" : "=r"(a) : "l"(p));
    return a;
}
// Swizzle for 32-byte rows: XOR row bit 2 into 16B-seg select bit.
__device__ __forceinline__ uint32_t sw32(uint32_t off) {
    return off ^ ((off >> 3) & 0x10);
}
__device__ __forceinline__ void ldsm_x4(uint32_t& r0, uint32_t& r1, uint32_t& r2, uint32_t& r3,
                                        uint32_t addr) {
    asm volatile("ldmatrix.sync.aligned.m8n8.x4.shared.b16 {%0,%1,%2,%3}, [%4];"
                 : "=r"(r0), "=r"(r1), "=r"(r2), "=r"(r3) : "r"(addr));
}
__device__ __forceinline__ void mma16816(float* d, const uint32_t* a, const uint32_t* b) {
    asm volatile(
        "mma.sync.aligned.m16n8k16.row.col.f32.bf16.bf16.f32 "
        "{%0,%1,%2,%3}, {%4,%5,%6,%7}, {%8,%9}, {%0,%1,%2,%3};"
        : "+f"(d[0]), "+f"(d[1]), "+f"(d[2]), "+f"(d[3])
        : "r"(a[0]), "r"(a[1]), "r"(a[2]), "r"(a[3]), "r"(b[0]), "r"(b[1]));
}

#define CP_ASYNC16(dst, src) \
    asm volatile("cp.async.cg.shared.global [%0], [%1], 16;" :: "r"(dst), "l"(src) : "memory")
#define CP_COMMIT()  asm volatile("cp.async.commit_group;" ::: "memory")
#define CP_WAIT2()   asm volatile("cp.async.wait_group 2;" ::: "memory")
#define CP_WAIT0()   asm volatile("cp.async.wait_group 0;" ::: "memory")

__device__ __forceinline__ void split2(const float4& v, uint2& hi, uint2& lo) {
    __nv_bfloat162 h0 = __floats2bfloat162_rn(v.x, v.y);
    __nv_bfloat162 h1 = __floats2bfloat162_rn(v.z, v.w);
    float r0 = v.x - __bfloat162float(__low2bfloat16(h0));
    float r1 = v.y - __bfloat162float(__high2bfloat16(h0));
    float r2 = v.z - __bfloat162float(__low2bfloat16(h1));
    float r3 = v.w - __bfloat162float(__high2bfloat16(h1));
    __nv_bfloat162 l0 = __floats2bfloat162_rn(r0, r1);
    __nv_bfloat162 l1 = __floats2bfloat162_rn(r2, r3);
    hi.x = *reinterpret_cast<uint32_t*>(&h0);
    hi.y = *reinterpret_cast<uint32_t*>(&h1);
    lo.x = *reinterpret_cast<uint32_t*>(&l0);
    lo.y = *reinterpret_cast<uint32_t*>(&l1);
}

__global__ __launch_bounds__(256, 3) void gemm_nt_mma(
    const __nv_bfloat16* __restrict__ Ahi, const __nv_bfloat16* __restrict__ Alo,
    const __nv_bfloat16* __restrict__ Bhi, const __nv_bfloat16* __restrict__ Blo,
    float* __restrict__ C, __nv_bfloat16* __restrict__ Chi, __nv_bfloat16* __restrict__ Clo,
    const float* __restrict__ bias,
    int M, int N, int K,
    long long strA, long long strB, long long strC)
{
    extern __shared__ __align__(1024) char smem[];
    const uint32_t sb = smem_u32(smem);
    const int tid = threadIdx.x, wid = tid >> 5, lane = tid & 31;
    const int row0 = blockIdx.y * 128, col0 = blockIdx.x * 64;

    Ahi += (size_t)blockIdx.z * strA;  Alo += (size_t)blockIdx.z * strA;
    Bhi += (size_t)blockIdx.z * strB;  Blo += (size_t)blockIdx.z * strB;

    // 4m x 2n warp grid, 32x32 warp tiles
    const int wm = wid & 3, wn = wid >> 2;
    const int m0w = wm * 32, n0w = wn * 32;

    // ---- cp.async loader indexing (BK=16 -> 32B rows) ----
    // A tiles: 128 rows x 2 segs = 256 segs -> 1/thread.
    const int la_row = tid >> 1;
    const int la_s   = tid & 1;
    // B tiles: 64 rows x 2 segs = 128 segs -> threads 0..127 only.
    const int lb_row = (tid & 127) >> 1;
    const int lb_s   = tid & 1;
    const bool do_b  = (tid < 128);

    const __nv_bfloat16* gAhi = Ahi + (size_t)(row0 + la_row) * K + la_s * 8;
    const __nv_bfloat16* gAlo = Alo + (size_t)(row0 + la_row) * K + la_s * 8;
    const __nv_bfloat16* gBhi = Bhi + (size_t)(col0 + lb_row) * K + lb_s * 8;
    const __nv_bfloat16* gBlo = Blo + (size_t)(col0 + lb_row) * K + lb_s * 8;

    // ldmatrix lane addressing (32B rows)
    const uint32_t a_lrow = (uint32_t)(lane & 15);
    const uint32_t a_lc16 = (uint32_t)(lane >> 4) * 16;
    const uint32_t b_lrow = (uint32_t)((lane & 7) + ((lane >> 4) & 1) * 8);
    const uint32_t b_lk16 = (uint32_t)((lane >> 3) & 1) * 16;

    float acc[2][4][4];
#pragma unroll
    for (int i = 0; i < 2; i++)
#pragma unroll
        for (int j = 0; j < 4; j++)
#pragma unroll
            for (int q = 0; q < 4; q++) acc[i][j][q] = 0.f;

    const int NCH = K >> 4;   // BK=16

    auto issue = [&](int ch) {
        if (ch < NCH) {
            const uint32_t st = sb + (uint32_t)((ch & 3) * STAGE_B);
            const long long koff = (long long)(ch << 4);
            unsigned long long pah =
                (unsigned long long)__cvta_generic_to_global((const void*)(gAhi + koff));
            unsigned long long pal =
                (unsigned long long)__cvta_generic_to_global((const void*)(gAlo + koff));
            uint32_t swa = sw32((uint32_t)(la_row * 32 + la_s * 16));
            CP_ASYNC16(st + AH_OFF + swa, pah);
            CP_ASYNC16(st + AL_OFF + swa, pal);
            if (do_b) {
                unsigned long long pbh =
                    (unsigned long long)__cvta_generic_to_global((const void*)(gBhi + koff));
                unsigned long long pbl =
                    (unsigned long long)__cvta_generic_to_global((const void*)(gBlo + koff));
                uint32_t swb = sw32((uint32_t)(lb_row * 32 + lb_s * 16));
                CP_ASYNC16(st + BH_OFF + swb, pbh);
                CP_ASYNC16(st + BL_OFF + swb, pbl);
            }
        }
        CP_COMMIT();
    };

    // One chunk (k16): 8 LDSM.x4 -> 24 MMAs in 3 bursts of 8.
    auto mma_ks = [&](uint32_t base) {
        uint32_t aFh[2][4], bFh[4][2], bFl[4][2];
#pragma unroll
        for (int mf = 0; mf < 2; mf++) {
            uint32_t off = (uint32_t)((m0w + mf * 16 + a_lrow) * 32 + a_lc16);
            ldsm_x4(aFh[mf][0], aFh[mf][1], aFh[mf][2], aFh[mf][3],
                    base + AH_OFF + sw32(off));
        }
#pragma unroll
        for (int nfp = 0; nfp < 2; nfp++) {
            uint32_t off = (uint32_t)((n0w + nfp * 16 + b_lrow) * 32 + b_lk16);
            uint32_t r0, r1, r2, r3;
            ldsm_x4(r0, r1, r2, r3, base + BH_OFF + sw32(off));
            bFh[nfp * 2][0] = r0;      bFh[nfp * 2][1] = r1;
            bFh[nfp * 2 + 1][0] = r2;  bFh[nfp * 2 + 1][1] = r3;
        }
#pragma unroll
        for (int nfp = 0; nfp < 2; nfp++) {
            uint32_t off = (uint32_t)((n0w + nfp * 16 + b_lrow) * 32 + b_lk16);
            uint32_t r0, r1, r2, r3;
            ldsm_x4(r0, r1, r2, r3, base + BL_OFF + sw32(off));
            bFl[nfp * 2][0] = r0;      bFl[nfp * 2][1] = r1;
            bFl[nfp * 2 + 1][0] = r2;  bFl[nfp * 2 + 1][1] = r3;
        }
        // burst 1: hh
#pragma unroll
        for (int mf = 0; mf < 2; mf++)
#pragma unroll
            for (int nf = 0; nf < 4; nf++) mma16816(acc[mf][nf], aFh[mf], bFh[nf]);
        // burst 2: hi(A) * lo(B)
#pragma unroll
        for (int mf = 0; mf < 2; mf++)
#pragma unroll
            for (int nf = 0; nf < 4; nf++) mma16816(acc[mf][nf], aFh[mf], bFl[nf]);
        // burst 3: lo(A) * hi(B)  (aFl loaded late to cap register liveness)
        uint32_t aFl[2][4];
#pragma unroll
        for (int mf = 0; mf < 2; mf++) {
            uint32_t off = (uint32_t)((m0w + mf * 16 + a_lrow) * 32 + a_lc16);
            ldsm_x4(aFl[mf][0], aFl[mf][1], aFl[mf][2], aFl[mf][3],
                    base + AL_OFF + sw32(off));
        }
#pragma unroll
        for (int mf = 0; mf < 2; mf++)
#pragma unroll
            for (int nf = 0; nf < 4; nf++) mma16816(acc[mf][nf], aFl[mf], bFh[nf]);
    };

    // prologue: 3 stages in flight
    issue(0);
    issue(1);
    issue(2);

    for (int ch = 0; ch < NCH; ch++) {
        const uint32_t cur = sb + (uint32_t)((ch & 3) * STAGE_B);
        CP_WAIT2();            // chunk ch resident (<=2 newer groups pending)
        __syncthreads();       // ONE barrier per chunk (ring distance 3 > drift 1)
        issue(ch + 3);         // overlaps with the MMA burst below
        mma_ks(cur);
    }
    CP_WAIT0();
    __syncthreads();

    // ---- epilogue: stage accums -> smem [128][68] -> coalesced writes ----
    float* eps = reinterpret_cast<float*>(smem);
    const int g = lane >> 2, c = lane & 3;
#pragma unroll
    for (int mf = 0; mf < 2; mf++)
#pragma unroll
        for (int nf = 0; nf < 4; nf++) {
            int r  = m0w + mf * 16 + g;
            int cc = n0w + nf * 8 + 2 * c;
            *reinterpret_cast<float2*>(&eps[r * 68 + cc]) =
                make_float2(acc[mf][nf][0], acc[mf][nf][1]);
            *reinterpret_cast<float2*>(&eps[(r + 8) * 68 + cc]) =
                make_float2(acc[mf][nf][2], acc[mf][nf][3]);
        }
    __syncthreads();

    if (Chi) {
        __nv_bfloat16* ph = Chi + (size_t)blockIdx.z * strC;
        __nv_bfloat16* pl = Clo + (size_t)blockIdx.z * strC;
#pragma unroll
        for (int it = 0; it < 8; it++) {
            int idx = tid + it * 256;
            int row = idx >> 4;
            int c4  = (idx & 15) << 2;
            float4 v = *reinterpret_cast<float4*>(&eps[row * 68 + c4]);
            float4 bz = *reinterpret_cast<const float4*>(&bias[col0 + c4]);
            v.x += bz.x; v.y += bz.y; v.z += bz.z; v.w += bz.w;
            uint2 hi, lo;
            split2(v, hi, lo);
            size_t o = (size_t)(row0 + row) * N + col0 + c4;
            *reinterpret_cast<uint2*>(&ph[o]) = hi;
            *reinterpret_cast<uint2*>(&pl[o]) = lo;
        }
    } else {
        float* Cb = C + (size_t)blockIdx.z * strC;
#pragma unroll
        for (int it = 0; it < 8; it++) {
            int idx = tid + it * 256;
            int row = idx >> 4;
            int c4  = (idx & 15) << 2;
            float4 v = *reinterpret_cast<float4*>(&eps[row * 68 + c4]);
            *reinterpret_cast<float4*>(&Cb[(size_t)(row0 + row) * N + col0 + c4]) = v;
        }
    }
}

// ============================================================
// prep_x: X -> X_hi/X_lo + XT_hi/XT_lo
// ============================================================
__global__ __launch_bounds__(256) void prep_x(
    const float* __restrict__ X,
    __nv_bfloat16* __restrict__ Xhi, __nv_bfloat16* __restrict__ Xlo,
    __nv_bfloat16* __restrict__ XThi, __nv_bfloat16* __restrict__ XTlo)
{
    __shared__ float t[32][33];
    const int b = blockIdx.z;
    const int s0 = blockIdx.x * 32, d0 = blockIdx.y * 32;
    const size_t bo = (size_t)b * SS * DD;
    const int tx = threadIdx.x, ty = threadIdx.y;
#pragma unroll
    for (int j = 0; j < 4; j++) {
        int s = s0 + ty + 8 * j;
        float v = X[bo + (size_t)s * DD + d0 + tx];
        t[ty + 8 * j][tx] = v;
        __nv_bfloat16 h = __float2bfloat16(v);
        Xhi[bo + (size_t)s * DD + d0 + tx] = h;
        Xlo[bo + (size_t)s * DD + d0 + tx] = __float2bfloat16(v - __bfloat162float(h));
    }
    __syncthreads();
#pragma unroll
    for (int j = 0; j < 4; j++) {
        int d = d0 + ty + 8 * j;
        float v = t[tx][ty + 8 * j];
        __nv_bfloat16 h = __float2bfloat16(v);
        XThi[bo + (size_t)d * SS + s0 + tx] = h;
        XTlo[bo + (size_t)d * SS + s0 + tx] = __float2bfloat16(v - __bfloat162float(h));
    }
}

__global__ __launch_bounds__(256) void split_w(
    const float* __restrict__ W,
    __nv_bfloat16* __restrict__ Whi, __nv_bfloat16* __restrict__ Wlo)
{
    int idx = blockIdx.x * 256 + threadIdx.x;
    float4 v = reinterpret_cast<const float4*>(W)[idx];
    uint2 hi, lo;
    split2(v, hi, lo);
    reinterpret_cast<uint2*>(Whi)[idx] = hi;
    reinterpret_cast<uint2*>(Wlo)[idx] = lo;
}

// ============================================================
// In-place row softmax + split bf16 out
// ============================================================
__device__ __forceinline__ float warp_max(float v) {
#pragma unroll
    for (int o = 16; o > 0; o >>= 1) v = fmaxf(v, __shfl_xor_sync(0xFFFFFFFFu, v, o));
    return v;
}
__device__ __forceinline__ float warp_sum(float v) {
#pragma unroll
    for (int o = 16; o > 0; o >>= 1) v += __shfl_xor_sync(0xFFFFFFFFu, v, o);
    return v;
}

__global__ __launch_bounds__(256) void softmax_rows(
    float* __restrict__ attn,
    __nv_bfloat16* __restrict__ Ahi, __nv_bfloat16* __restrict__ Alo)
{
    __shared__ float red[8];
    const size_t ro = (size_t)blockIdx.x * SS;
    float* row = attn + ro;
    const int tid = threadIdx.x, lane = tid & 31, wid = tid >> 5;

    float4 v[2];
    v[0] = *reinterpret_cast<const float4*>(&row[tid * 4]);
    v[1] = *reinterpret_cast<const float4*>(&row[(tid + 256) * 4]);

    float mx = -INFINITY;
#pragma unroll
    for (int i = 0; i < 2; i++)
        mx = fmaxf(mx, fmaxf(fmaxf(v[i].x, v[i].y), fmaxf(v[i].z, v[i].w)));
    mx = warp_max(mx);
    if (lane == 0) red[wid] = mx;
    __syncthreads();
    if (wid == 0) {
        float t = (lane < 8) ? red[lane] : -INFINITY;
        t = warp_max(t);
        if (lane == 0) red[0] = t;
    }
    __syncthreads();
    mx = red[0];
    __syncthreads();

    float s = 0.f;
#pragma unroll
    for (int i = 0; i < 2; i++) {
        v[i].x = expf(v[i].x - mx); s += v[i].x;
        v[i].y = expf(v[i].y - mx); s += v[i].y;
        v[i].z = expf(v[i].z - mx); s += v[i].z;
        v[i].w = expf(v[i].w - mx); s += v[i].w;
    }
    s = warp_sum(s);
    if (lane == 0) red[wid] = s;
    __syncthreads();
    if (wid == 0) {
        float t = (lane < 8) ? red[lane] : 0.0f;
        t = warp_sum(t);
        if (lane == 0) red[0] = t;
    }
    __syncthreads();
    float inv = 1.0f / red[0];

#pragma unroll
    for (int i = 0; i < 2; i++) { v[i].x *= inv; v[i].y *= inv; v[i].z *= inv; v[i].w *= inv; }
    *reinterpret_cast<float4*>(&row[tid * 4])         = v[0];
    *reinterpret_cast<float4*>(&row[(tid + 256) * 4]) = v[1];

    uint2 hi, lo;
    split2(v[0], hi, lo);
    *reinterpret_cast<uint2*>(&Ahi[ro + tid * 4]) = hi;
    *reinterpret_cast<uint2*>(&Alo[ro + tid * 4]) = lo;
    split2(v[1], hi, lo);
    *reinterpret_cast<uint2*>(&Ahi[ro + (tid + 256) * 4]) = hi;
    *reinterpret_cast<uint2*>(&Alo[ro + (tid + 256) * 4]) = lo;
}

// ============================================================
// kernel_launch
// ============================================================
extern "C" void kernel_launch(void* const* d_in, const int* in_sizes, int n_in,
                              void* d_out, int out_size)
{
    const float* X    = (const float*)d_in[0];
    const float* W    = (const float*)d_in[1];
    const float* bias = (const float*)d_in[2];

    float* ctx  = (float*)d_out;                           // [8,2048,1024]
    float* attn = (float*)d_out + (size_t)BB * SS * DD;    // [8,2048,2048]

    __nv_bfloat16 *xhi, *xlo, *xthi, *xtlo, *whi, *wlo, *phi, *plo, *ahi, *alo;
    cudaGetSymbolAddress((void**)&xhi,  g_xhi);
    cudaGetSymbolAddress((void**)&xlo,  g_xlo);
    cudaGetSymbolAddress((void**)&xthi, g_xthi);
    cudaGetSymbolAddress((void**)&xtlo, g_xtlo);
    cudaGetSymbolAddress((void**)&whi,  g_whi);
    cudaGetSymbolAddress((void**)&wlo,  g_wlo);
    cudaGetSymbolAddress((void**)&phi,  g_phi);
    cudaGetSymbolAddress((void**)&plo,  g_plo);
    cudaGetSymbolAddress((void**)&ahi,  g_ahi);
    cudaGetSymbolAddress((void**)&alo,  g_alo);

    cudaFuncSetAttribute(gemm_nt_mma, cudaFuncAttributeMaxDynamicSharedMemorySize, GEMM_SMEM);

    const long long sXD = (long long)SS * DD;
    const long long sAA = (long long)SS * SS;

    {
        dim3 grid(SS / 32, DD / 32, BB);
        prep_x<<<grid, dim3(32, 8)>>>(X, xhi, xlo, xthi, xtlo);
    }
    split_w<<<(DD * DD / 4) / 256, 256>>>(W, whi, wlo);

    // GEMM1: proj = X * W^T + b  -> split bf16 pair
    {
        dim3 grid(DD / 64, (BB * SS) / 128, 1);
        gemm_nt_mma<<<grid, 256, GEMM_SMEM>>>(xhi, xlo, whi, wlo,
                                              nullptr, phi, plo, bias,
                                              BB * SS, DD, DD, 0, 0, 0);
    }
    // GEMM2: attn[b] = X[b] * proj[b]^T  (fp32 out)
    {
        dim3 grid(SS / 64, SS / 128, BB);
        gemm_nt_mma<<<grid, 256, GEMM_SMEM>>>(xhi, xlo, phi, plo,
                                              attn, nullptr, nullptr, nullptr,
                                              SS, SS, DD, sXD, sXD, sAA);
    }
    softmax_rows<<<BB * SS, 256>>>(attn, ahi, alo);
    // GEMM3: ctx[b] = attn[b] * XT[b]^T  (fp32 out)
    {
        dim3 grid(DD / 64, SS / 128, BB);
        gemm_nt_mma<<<grid, 256, GEMM_SMEM>>>(ahi, alo, xthi, xtlo,
                                              ctx, nullptr, nullptr, nullptr,
                                              SS, DD, SS, sAA, sXD, sXD);
    }
}

// round 13
// speedup vs baseline: 1.1899x; 1.0454x over previous
#include <cuda_runtime.h>
#include <cuda_bf16.h>
#include <math.h>
#include <stdint.h>

// Problem shape (fixed by the dataset)
#define BB 8
#define SS 2048
#define DD 1024

// Pre-split bf16 operand arrays (device globals — allocation-guard-safe)
__device__ __nv_bfloat16 g_xhi[(size_t)BB * SS * DD];
__device__ __nv_bfloat16 g_xlo[(size_t)BB * SS * DD];
__device__ __nv_bfloat16 g_xthi[(size_t)BB * SS * DD];
__device__ __nv_bfloat16 g_xtlo[(size_t)BB * SS * DD];
__device__ __nv_bfloat16 g_whi[(size_t)DD * DD];
__device__ __nv_bfloat16 g_wlo[(size_t)DD * DD];
__device__ __nv_bfloat16 g_phi[(size_t)BB * SS * DD];
__device__ __nv_bfloat16 g_plo[(size_t)BB * SS * DD];
__device__ __nv_bfloat16 g_ahi[(size_t)BB * SS * SS];
__device__ __nv_bfloat16 g_alo[(size_t)BB * SS * SS];

// ============================================================
// R13 GEMM: R12 structure (128x64 CTA tile, BK=16, 4-stage ring, one
// barrier/chunk, 3 CTAs/SM, 32x32 warp tiles) with hot-loop ALU stripped:
//   - LDSM swizzled offsets hoisted to registers (loop-invariant)
//   - cvta done once; issue() = one u64 add per tile
//   - main loop unrolled x4 with precomputed stage bases
// ============================================================

#define AH_OFF 0
#define AL_OFF 4096
#define BH_OFF 8192
#define BL_OFF 10240
#define STAGE_B 12288
#define GEMM_SMEM (4 * STAGE_B)   // 48 KB (>= epilogue's 34.8 KB)

__device__ __forceinline__ uint32_t smem_u32(const void* p) {
    uint32_t a;
    asm("{ .reg .u64 t; cvta.to.shared.u64 t, %1; cvt.u32.u64 %0, t; }" : "=r"(a) : "l"(p));
    return a;
}
__device__ __forceinline__ uint32_t sw32(uint32_t off) {
    return off ^ ((off >> 3) & 0x10);
}
__device__ __forceinline__ void ldsm_x4(uint32_t& r0, uint32_t& r1, uint32_t& r2, uint32_t& r3,
                                        uint32_t addr) {
    asm volatile("ldmatrix.sync.aligned.m8n8.x4.shared.b16 {%0,%1,%2,%3}, [%4];"
                 : "=r"(r0), "=r"(r1), "=r"(r2), "=r"(r3) : "r"(addr));
}
__device__ __forceinline__ void mma16816(float* d, const uint32_t* a, const uint32_t* b) {
    asm volatile(
        "mma.sync.aligned.m16n8k16.row.col.f32.bf16.bf16.f32 "
        "{%0,%1,%2,%3}, {%4,%5,%6,%7}, {%8,%9}, {%0,%1,%2,%3};"
        : "+f"(d[0]), "+f"(d[1]), "+f"(d[2]), "+f"(d[3])
        : "r"(a[0]), "r"(a[1]), "r"(a[2]), "r"(a[3]), "r"(b[0]), "r"(b[1]));
}

#define CP_ASYNC16(dst, src) \
    asm volatile("cp.async.cg.shared.global [%0], [%1], 16;" :: "r"(dst), "l"(src) : "memory")
#define CP_COMMIT()  asm volatile("cp.async.commit_group;" ::: "memory")
#define CP_WAIT2()   asm volatile("cp.async.wait_group 2;" ::: "memory")
#define CP_WAIT0()   asm volatile("cp.async.wait_group 0;" ::: "memory")

__device__ __forceinline__ void split2(const float4& v, uint2& hi, uint2& lo) {
    __nv_bfloat162 h0 = __floats2bfloat162_rn(v.x, v.y);
    __nv_bfloat162 h1 = __floats2bfloat162_rn(v.z, v.w);
    float r0 = v.x - __bfloat162float(__low2bfloat16(h0));
    float r1 = v.y - __bfloat162float(__high2bfloat16(h0));
    float r2 = v.z - __bfloat162float(__low2bfloat16(h1));
    float r3 = v.w - __bfloat162float(__high2bfloat16(h1));
    __nv_bfloat162 l0 = __floats2bfloat162_rn(r0, r1);
    __nv_bfloat162 l1 = __floats2bfloat162_rn(r2, r3);
    hi.x = *reinterpret_cast<uint32_t*>(&h0);
    hi.y = *reinterpret_cast<uint32_t*>(&h1);
    lo.x = *reinterpret_cast<uint32_t*>(&l0);
    lo.y = *reinterpret_cast<uint32_t*>(&l1);
}

__global__ __launch_bounds__(256, 3) void gemm_nt_mma(
    const __nv_bfloat16* __restrict__ Ahi, const __nv_bfloat16* __restrict__ Alo,
    const __nv_bfloat16* __restrict__ Bhi, const __nv_bfloat16* __restrict__ Blo,
    float* __restrict__ C, __nv_bfloat16* __restrict__ Chi, __nv_bfloat16* __restrict__ Clo,
    const float* __restrict__ bias,
    int M, int N, int K,
    long long strA, long long strB, long long strC)
{
    extern __shared__ __align__(1024) char smem[];
    const uint32_t sb = smem_u32(smem);
    const int tid = threadIdx.x, wid = tid >> 5, lane = tid & 31;
    const int row0 = blockIdx.y * 128, col0 = blockIdx.x * 64;

    Ahi += (size_t)blockIdx.z * strA;  Alo += (size_t)blockIdx.z * strA;
    Bhi += (size_t)blockIdx.z * strB;  Blo += (size_t)blockIdx.z * strB;

    // 4m x 2n warp grid, 32x32 warp tiles
    const int wm = wid & 3, wn = wid >> 2;
    const int m0w = wm * 32, n0w = wn * 32;

    // ---- cp.async loader indexing (BK=16 -> 32B rows) ----
    const int la_row = tid >> 1;
    const int la_s   = tid & 1;
    const int lb_row = (tid & 127) >> 1;
    const int lb_s   = tid & 1;
    const bool do_b  = (tid < 128);

    // Hoisted: global pointers as u64 (cvta once)
    const unsigned long long pah = (unsigned long long)__cvta_generic_to_global(
        (const void*)(Ahi + (size_t)(row0 + la_row) * K + la_s * 8));
    const unsigned long long pal = (unsigned long long)__cvta_generic_to_global(
        (const void*)(Alo + (size_t)(row0 + la_row) * K + la_s * 8));
    const unsigned long long pbh = (unsigned long long)__cvta_generic_to_global(
        (const void*)(Bhi + (size_t)(col0 + lb_row) * K + lb_s * 8));
    const unsigned long long pbl = (unsigned long long)__cvta_generic_to_global(
        (const void*)(Blo + (size_t)(col0 + lb_row) * K + lb_s * 8));

    // Hoisted: swizzled store offsets
    const uint32_t swa = sw32((uint32_t)(la_row * 32 + la_s * 16));
    const uint32_t swb = sw32((uint32_t)(lb_row * 32 + lb_s * 16));

    // Hoisted: ldmatrix swizzled offsets (loop-invariant)
    const uint32_t a_lrow = (uint32_t)(lane & 15);
    const uint32_t a_lc16 = (uint32_t)(lane >> 4) * 16;
    const uint32_t b_lrow = (uint32_t)((lane & 7) + ((lane >> 4) & 1) * 8);
    const uint32_t b_lk16 = (uint32_t)((lane >> 3) & 1) * 16;
    const uint32_t offA0 = sw32((uint32_t)((m0w + a_lrow) * 32 + a_lc16));
    const uint32_t offA1 = sw32((uint32_t)((m0w + 16 + a_lrow) * 32 + a_lc16));
    const uint32_t offB0 = sw32((uint32_t)((n0w + b_lrow) * 32 + b_lk16));
    const uint32_t offB1 = sw32((uint32_t)((n0w + 16 + b_lrow) * 32 + b_lk16));

    // Hoisted: stage base addresses
    const uint32_t stage0 = sb;
    const uint32_t stage1 = sb + STAGE_B;
    const uint32_t stage2 = sb + 2 * STAGE_B;
    const uint32_t stage3 = sb + 3 * STAGE_B;

    float acc[2][4][4];
#pragma unroll
    for (int i = 0; i < 2; i++)
#pragma unroll
        for (int j = 0; j < 4; j++)
#pragma unroll
            for (int q = 0; q < 4; q++) acc[i][j][q] = 0.f;

    const int NCH = K >> 4;   // BK=16; 64 or 128 here (divisible by 4)

    auto issue = [&](int ch, uint32_t st) {
        if (ch < NCH) {
            const unsigned long long koff = (unsigned long long)(ch << 5);  // bytes
            CP_ASYNC16(st + AH_OFF + swa, pah + koff);
            CP_ASYNC16(st + AL_OFF + swa, pal + koff);
            if (do_b) {
                CP_ASYNC16(st + BH_OFF + swb, pbh + koff);
                CP_ASYNC16(st + BL_OFF + swb, pbl + koff);
            }
        }
        CP_COMMIT();
    };

    // One chunk (k16): 8 LDSM.x4 -> 24 MMAs in 3 bursts of 8.
    auto mma_ks = [&](uint32_t base) {
        uint32_t aFh[2][4], bFh[4][2], bFl[4][2];
        ldsm_x4(aFh[0][0], aFh[0][1], aFh[0][2], aFh[0][3], base + AH_OFF + offA0);
        ldsm_x4(aFh[1][0], aFh[1][1], aFh[1][2], aFh[1][3], base + AH_OFF + offA1);
        {
            uint32_t r0, r1, r2, r3;
            ldsm_x4(r0, r1, r2, r3, base + BH_OFF + offB0);
            bFh[0][0] = r0; bFh[0][1] = r1; bFh[1][0] = r2; bFh[1][1] = r3;
            ldsm_x4(r0, r1, r2, r3, base + BH_OFF + offB1);
            bFh[2][0] = r0; bFh[2][1] = r1; bFh[3][0] = r2; bFh[3][1] = r3;
            ldsm_x4(r0, r1, r2, r3, base + BL_OFF + offB0);
            bFl[0][0] = r0; bFl[0][1] = r1; bFl[1][0] = r2; bFl[1][1] = r3;
            ldsm_x4(r0, r1, r2, r3, base + BL_OFF + offB1);
            bFl[2][0] = r0; bFl[2][1] = r1; bFl[3][0] = r2; bFl[3][1] = r3;
        }
        // burst 1: hh
#pragma unroll
        for (int mf = 0; mf < 2; mf++)
#pragma unroll
            for (int nf = 0; nf < 4; nf++) mma16816(acc[mf][nf], aFh[mf], bFh[nf]);
        // burst 2: hi(A) * lo(B)
#pragma unroll
        for (int mf = 0; mf < 2; mf++)
#pragma unroll
            for (int nf = 0; nf < 4; nf++) mma16816(acc[mf][nf], aFh[mf], bFl[nf]);
        // burst 3: lo(A) * hi(B)
        uint32_t aFl[2][4];
        ldsm_x4(aFl[0][0], aFl[0][1], aFl[0][2], aFl[0][3], base + AL_OFF + offA0);
        ldsm_x4(aFl[1][0], aFl[1][1], aFl[1][2], aFl[1][3], base + AL_OFF + offA1);
#pragma unroll
        for (int mf = 0; mf < 2; mf++)
#pragma unroll
            for (int nf = 0; nf < 4; nf++) mma16816(acc[mf][nf], aFl[mf], bFh[nf]);
    };

    // prologue: 3 stages in flight
    issue(0, stage0);
    issue(1, stage1);
    issue(2, stage2);

    const uint32_t stages[4] = {stage0, stage1, stage2, stage3};
    for (int ch4 = 0; ch4 < NCH; ch4 += 4) {
#pragma unroll
        for (int u = 0; u < 4; u++) {
            CP_WAIT2();
            __syncthreads();
            issue(ch4 + u + 3, stages[(u + 3) & 3]);
            mma_ks(stages[u]);
        }
    }
    CP_WAIT0();
    __syncthreads();

    // ---- epilogue: stage accums -> smem [128][68] -> coalesced writes ----
    float* eps = reinterpret_cast<float*>(smem);
    const int g = lane >> 2, c = lane & 3;
#pragma unroll
    for (int mf = 0; mf < 2; mf++)
#pragma unroll
        for (int nf = 0; nf < 4; nf++) {
            int r  = m0w + mf * 16 + g;
            int cc = n0w + nf * 8 + 2 * c;
            *reinterpret_cast<float2*>(&eps[r * 68 + cc]) =
                make_float2(acc[mf][nf][0], acc[mf][nf][1]);
            *reinterpret_cast<float2*>(&eps[(r + 8) * 68 + cc]) =
                make_float2(acc[mf][nf][2], acc[mf][nf][3]);
        }
    __syncthreads();

    if (Chi) {
        __nv_bfloat16* ph = Chi + (size_t)blockIdx.z * strC;
        __nv_bfloat16* pl = Clo + (size_t)blockIdx.z * strC;
#pragma unroll
        for (int it = 0; it < 8; it++) {
            int idx = tid + it * 256;
            int row = idx >> 4;
            int c4  = (idx & 15) << 2;
            float4 v = *reinterpret_cast<float4*>(&eps[row * 68 + c4]);
            float4 bz = *reinterpret_cast<const float4*>(&bias[col0 + c4]);
            v.x += bz.x; v.y += bz.y; v.z += bz.z; v.w += bz.w;
            uint2 hi, lo;
            split2(v, hi, lo);
            size_t o = (size_t)(row0 + row) * N + col0 + c4;
            *reinterpret_cast<uint2*>(&ph[o]) = hi;
            *reinterpret_cast<uint2*>(&pl[o]) = lo;
        }
    } else {
        float* Cb = C + (size_t)blockIdx.z * strC;
#pragma unroll
        for (int it = 0; it < 8; it++) {
            int idx = tid + it * 256;
            int row = idx >> 4;
            int c4  = (idx & 15) << 2;
            float4 v = *reinterpret_cast<float4*>(&eps[row * 68 + c4]);
            *reinterpret_cast<float4*>(&Cb[(size_t)(row0 + row) * N + col0 + c4]) = v;
        }
    }
}

// ============================================================
// prep_x: X -> X_hi/X_lo + XT_hi/XT_lo
// ============================================================
__global__ __launch_bounds__(256) void prep_x(
    const float* __restrict__ X,
    __nv_bfloat16* __restrict__ Xhi, __nv_bfloat16* __restrict__ Xlo,
    __nv_bfloat16* __restrict__ XThi, __nv_bfloat16* __restrict__ XTlo)
{
    __shared__ float t[32][33];
    const int b = blockIdx.z;
    const int s0 = blockIdx.x * 32, d0 = blockIdx.y * 32;
    const size_t bo = (size_t)b * SS * DD;
    const int tx = threadIdx.x, ty = threadIdx.y;
#pragma unroll
    for (int j = 0; j < 4; j++) {
        int s = s0 + ty + 8 * j;
        float v = X[bo + (size_t)s * DD + d0 + tx];
        t[ty + 8 * j][tx] = v;
        __nv_bfloat16 h = __float2bfloat16(v);
        Xhi[bo + (size_t)s * DD + d0 + tx] = h;
        Xlo[bo + (size_t)s * DD + d0 + tx] = __float2bfloat16(v - __bfloat162float(h));
    }
    __syncthreads();
#pragma unroll
    for (int j = 0; j < 4; j++) {
        int d = d0 + ty + 8 * j;
        float v = t[tx][ty + 8 * j];
        __nv_bfloat16 h = __float2bfloat16(v);
        XThi[bo + (size_t)d * SS + s0 + tx] = h;
        XTlo[bo + (size_t)d * SS + s0 + tx] = __float2bfloat16(v - __bfloat162float(h));
    }
}

__global__ __launch_bounds__(256) void split_w(
    const float* __restrict__ W,
    __nv_bfloat16* __restrict__ Whi, __nv_bfloat16* __restrict__ Wlo)
{
    int idx = blockIdx.x * 256 + threadIdx.x;
    float4 v = reinterpret_cast<const float4*>(W)[idx];
    uint2 hi, lo;
    split2(v, hi, lo);
    reinterpret_cast<uint2*>(Whi)[idx] = hi;
    reinterpret_cast<uint2*>(Wlo)[idx] = lo;
}

// ============================================================
// In-place row softmax + split bf16 out
// ============================================================
__device__ __forceinline__ float warp_max(float v) {
#pragma unroll
    for (int o = 16; o > 0; o >>= 1) v = fmaxf(v, __shfl_xor_sync(0xFFFFFFFFu, v, o));
    return v;
}
__device__ __forceinline__ float warp_sum(float v) {
#pragma unroll
    for (int o = 16; o > 0; o >>= 1) v += __shfl_xor_sync(0xFFFFFFFFu, v, o);
    return v;
}

__global__ __launch_bounds__(256) void softmax_rows(
    float* __restrict__ attn,
    __nv_bfloat16* __restrict__ Ahi, __nv_bfloat16* __restrict__ Alo)
{
    __shared__ float red[8];
    const size_t ro = (size_t)blockIdx.x * SS;
    float* row = attn + ro;
    const int tid = threadIdx.x, lane = tid & 31, wid = tid >> 5;

    float4 v[2];
    v[0] = *reinterpret_cast<const float4*>(&row[tid * 4]);
    v[1] = *reinterpret_cast<const float4*>(&row[(tid + 256) * 4]);

    float mx = -INFINITY;
#pragma unroll
    for (int i = 0; i < 2; i++)
        mx = fmaxf(mx, fmaxf(fmaxf(v[i].x, v[i].y), fmaxf(v[i].z, v[i].w)));
    mx = warp_max(mx);
    if (lane == 0) red[wid] = mx;
    __syncthreads();
    if (wid == 0) {
        float t = (lane < 8) ? red[lane] : -INFINITY;
        t = warp_max(t);
        if (lane == 0) red[0] = t;
    }
    __syncthreads();
    mx = red[0];
    __syncthreads();

    float s = 0.f;
#pragma unroll
    for (int i = 0; i < 2; i++) {
        v[i].x = expf(v[i].x - mx); s += v[i].x;
        v[i].y = expf(v[i].y - mx); s += v[i].y;
        v[i].z = expf(v[i].z - mx); s += v[i].z;
        v[i].w = expf(v[i].w - mx); s += v[i].w;
    }
    s = warp_sum(s);
    if (lane == 0) red[wid] = s;
    __syncthreads();
    if (wid == 0) {
        float t = (lane < 8) ? red[lane] : 0.0f;
        t = warp_sum(t);
        if (lane == 0) red[0] = t;
    }
    __syncthreads();
    float inv = 1.0f / red[0];

#pragma unroll
    for (int i = 0; i < 2; i++) { v[i].x *= inv; v[i].y *= inv; v[i].z *= inv; v[i].w *= inv; }
    *reinterpret_cast<float4*>(&row[tid * 4])         = v[0];
    *reinterpret_cast<float4*>(&row[(tid + 256) * 4]) = v[1];

    uint2 hi, lo;
    split2(v[0], hi, lo);
    *reinterpret_cast<uint2*>(&Ahi[ro + tid * 4]) = hi;
    *reinterpret_cast<uint2*>(&Alo[ro + tid * 4]) = lo;
    split2(v[1], hi, lo);
    *reinterpret_cast<uint2*>(&Ahi[ro + (tid + 256) * 4]) = hi;
    *reinterpret_cast<uint2*>(&Alo[ro + (tid + 256) * 4]) = lo;
}

// ============================================================
// kernel_launch
// ============================================================
extern "C" void kernel_launch(void* const* d_in, const int* in_sizes, int n_in,
                              void* d_out, int out_size)
{
    const float* X    = (const float*)d_in[0];
    const float* W    = (const float*)d_in[1];
    const float* bias = (const float*)d_in[2];

    float* ctx  = (float*)d_out;                           // [8,2048,1024]
    float* attn = (float*)d_out + (size_t)BB * SS * DD;    // [8,2048,2048]

    __nv_bfloat16 *xhi, *xlo, *xthi, *xtlo, *whi, *wlo, *phi, *plo, *ahi, *alo;
    cudaGetSymbolAddress((void**)&xhi,  g_xhi);
    cudaGetSymbolAddress((void**)&xlo,  g_xlo);
    cudaGetSymbolAddress((void**)&xthi, g_xthi);
    cudaGetSymbolAddress((void**)&xtlo, g_xtlo);
    cudaGetSymbolAddress((void**)&whi,  g_whi);
    cudaGetSymbolAddress((void**)&wlo,  g_wlo);
    cudaGetSymbolAddress((void**)&phi,  g_phi);
    cudaGetSymbolAddress((void**)&plo,  g_plo);
    cudaGetSymbolAddress((void**)&ahi,  g_ahi);
    cudaGetSymbolAddress((void**)&alo,  g_alo);

    cudaFuncSetAttribute(gemm_nt_mma, cudaFuncAttributeMaxDynamicSharedMemorySize, GEMM_SMEM);

    const long long sXD = (long long)SS * DD;
    const long long sAA = (long long)SS * SS;

    {
        dim3 grid(SS / 32, DD / 32, BB);
        prep_x<<<grid, dim3(32, 8)>>>(X, xhi, xlo, xthi, xtlo);
    }
    split_w<<<(DD * DD / 4) / 256, 256>>>(W, whi, wlo);

    // GEMM1: proj = X * W^T + b  -> split bf16 pair
    {
        dim3 grid(DD / 64, (BB * SS) / 128, 1);
        gemm_nt_mma<<<grid, 256, GEMM_SMEM>>>(xhi, xlo, whi, wlo,
                                              nullptr, phi, plo, bias,
                                              BB * SS, DD, DD, 0, 0, 0);
    }
    // GEMM2: attn[b] = X[b] * proj[b]^T  (fp32 out)
    {
        dim3 grid(SS / 64, SS / 128, BB);
        gemm_nt_mma<<<grid, 256, GEMM_SMEM>>>(xhi, xlo, phi, plo,
                                              attn, nullptr, nullptr, nullptr,
                                              SS, SS, DD, sXD, sXD, sAA);
    }
    softmax_rows<<<BB * SS, 256>>>(attn, ahi, alo);
    // GEMM3: ctx[b] = attn[b] * XT[b]^T  (fp32 out)
    {
        dim3 grid(DD / 64, SS / 128, BB);
        gemm_nt_mma<<<grid, 256, GEMM_SMEM>>>(ahi, alo, xthi, xtlo,
                                              ctx, nullptr, nullptr, nullptr,
                                              SS, DD, SS, sAA, sXD, sXD);
    }
}